// round 1
// baseline (speedup 1.0000x reference)
#include <cuda_runtime.h>

// Problem constants
#define NBATCH 32
#define NCHAN  3
#define NIMG   (NBATCH * NCHAN)   // 96 independent 512x512 images
#define H      512
#define W      512
#define WP     544                // padded row width: 12 left zeros, 512 body, 20 right zeros
#define KS     21
#define KTAPS  (KS * KS)          // 441

// Padded-input scratch (allowed: __device__ global array, no runtime alloc)
__device__ float g_xpad[(size_t)NIMG * H * WP];

// ---- packed fp32x2 helpers ----------------------------------------------
__device__ __forceinline__ void ffma2(unsigned long long& d,
                                      unsigned long long a,
                                      unsigned long long b) {
    asm("fma.rn.f32x2 %0, %1, %2, %0;" : "+l"(d) : "l"(a), "l"(b));
}

__device__ __forceinline__ unsigned long long pk(float lo, float hi) {
    unsigned long long r;
    asm("mov.b64 %0, {%1, %2};" : "=l"(r) : "f"(lo), "f"(hi));
    return r;
}

__device__ __forceinline__ void unpk(unsigned long long v, float& lo, float& hi) {
    asm("mov.b64 {%0, %1}, %2;" : "=f"(lo), "=f"(hi) : "l"(v));
}

// ---- kernel 1: zero-pad x into g_xpad (x-direction only) ----------------
// Layout: g_xpad[img][y][px], px = gx + 12. px in [0,12) and [524,544) are 0.
__global__ void prepad_kernel(const float* __restrict__ x) {
    int idx = blockIdx.x * 256 + threadIdx.x;   // one float4 (quad) per thread
    // total quads = NIMG*H*(WP/4) = 96*512*136
    int q  = idx % (WP / 4);                     // quad within padded row
    int ry = idx / (WP / 4);                     // img*H + y
    float4 val = make_float4(0.f, 0.f, 0.f, 0.f);
    if (q >= 3 && q < 131) {                     // body: px 12..523
        val = *reinterpret_cast<const float4*>(x + (size_t)ry * W + q * 4 - 12);
    }
    *reinterpret_cast<float4*>(g_xpad + (size_t)ry * WP + q * 4) = val;
}

// ---- kernel 2: depthwise conv, f32x2 packed FMA -------------------------
// CTA tile: 64 cols x 64 rows of one image. 256 threads.
// Thread: lane_x = tid&7 (8 cols each), lane_y = tid>>3 (2 rows each).
__global__ __launch_bounds__(256) void conv_kernel(const float* __restrict__ d_k,
                                                   float* __restrict__ d_out) {
    __shared__ float2 k2s[KTAPS];   // kernel duplicated (k,k) for f32x2 b-operand

    const int tid = threadIdx.x;
    const int img = blockIdx.z;

    // load this image's kernel (kernel index = batch = img/3), duplicate lanes
    const float* kptr = d_k + (size_t)(img / NCHAN) * KTAPS;
    for (int i = tid; i < KTAPS; i += 256) {
        float kv = kptr[i];
        k2s[i] = make_float2(kv, kv);
    }
    __syncthreads();

    const int lane_x = tid & 7;
    const int lane_y = tid >> 3;
    const int x0   = blockIdx.x * 64 + lane_x * 8;   // first of 8 output cols
    const int ytop = blockIdx.y * 64 + lane_y * 2;   // first of 2 output rows

    // padded base: element i of the row segment corresponds to gx = x0 - 12 + i,
    // i.e. padded px = x0 + i.
    const float* base = g_xpad + (size_t)img * H * WP + x0;

    unsigned long long acc[8];   // [0..3]: row ytop pairs, [4..7]: row ytop+1
#pragma unroll
    for (int p = 0; p < 8; ++p) acc[p] = 0ull;

    for (int r = 0; r < 22; ++r) {            // input rows ytop-10 .. ytop+11
        const int iy = ytop + r - 10;
        if (iy < 0 || iy >= H) continue;       // y zero-padding == skip

        // load 32 floats of this padded row (8 aligned float4)
        float4 v[8];
        const float4* src = reinterpret_cast<const float4*>(base + (size_t)iy * WP);
#pragma unroll
        for (int j = 0; j < 8; ++j) v[j] = src[j];

        float fl[32];
#pragma unroll
        for (int j = 0; j < 8; ++j) {
            fl[4 * j + 0] = v[j].x; fl[4 * j + 1] = v[j].y;
            fl[4 * j + 2] = v[j].z; fl[4 * j + 3] = v[j].w;
        }

        // aligned pairs e[j]=(fl[2j],fl[2j+1]); shifted pairs g[j]=(fl[2j+1],fl[2j+2])
        unsigned long long e[15], g[14];
#pragma unroll
        for (int j = 1; j < 15; ++j) e[j] = pk(fl[2 * j], fl[2 * j + 1]);
#pragma unroll
        for (int j = 1; j < 14; ++j) g[j] = pk(fl[2 * j + 1], fl[2 * j + 2]);

        // contribution to output row ytop (dy = r), valid for r in [0,20]
        if (r <= 20) {
            const int dy = r;
#pragma unroll
            for (int dx = 0; dx < 21; ++dx) {
                unsigned long long kk =
                    *reinterpret_cast<const unsigned long long*>(&k2s[dy * 21 + dx]);
#pragma unroll
                for (int p = 0; p < 4; ++p) {
                    const int i2 = 2 * p + dx + 2;   // fl index of pair start
                    unsigned long long a = (i2 & 1) ? g[(i2 - 1) >> 1] : e[i2 >> 1];
                    ffma2(acc[p], a, kk);
                }
            }
        }
        // contribution to output row ytop+1 (dy = r-1), valid for r in [1,21]
        if (r >= 1) {
            const int dy = r - 1;
#pragma unroll
            for (int dx = 0; dx < 21; ++dx) {
                unsigned long long kk =
                    *reinterpret_cast<const unsigned long long*>(&k2s[dy * 21 + dx]);
#pragma unroll
                for (int p = 0; p < 4; ++p) {
                    const int i2 = 2 * p + dx + 2;
                    unsigned long long a = (i2 & 1) ? g[(i2 - 1) >> 1] : e[i2 >> 1];
                    ffma2(acc[4 + p], a, kk);
                }
            }
        }
    }

    // unpack + store: 2 rows x 8 cols = 4 float4 stores
    float res[16];
#pragma unroll
    for (int p = 0; p < 8; ++p) unpk(acc[p], res[2 * p], res[2 * p + 1]);

    float* outp = d_out + (size_t)img * H * W + (size_t)ytop * W + x0;
    reinterpret_cast<float4*>(outp)[0] = make_float4(res[0], res[1], res[2], res[3]);
    reinterpret_cast<float4*>(outp)[1] = make_float4(res[4], res[5], res[6], res[7]);
    reinterpret_cast<float4*>(outp + W)[0] = make_float4(res[8], res[9], res[10], res[11]);
    reinterpret_cast<float4*>(outp + W)[1] = make_float4(res[12], res[13], res[14], res[15]);
}

// ---- launch --------------------------------------------------------------
extern "C" void kernel_launch(void* const* d_in, const int* in_sizes, int n_in,
                              void* d_out, int out_size) {
    const float* x = (const float*)d_in[0];   // (32,3,512,512) fp32
    const float* k = (const float*)d_in[1];   // (32,1,21,21)  fp32
    float* out = (float*)d_out;

    // 1) pad input rows into scratch
    const int total_quads = NIMG * H * (WP / 4);     // 6,684,672
    prepad_kernel<<<total_quads / 256, 256>>>(x);

    // 2) main conv
    dim3 grid(W / 64, H / 64, NIMG);                 // (8, 8, 96)
    conv_kernel<<<grid, 256>>>(k, out);
}